// round 11
// baseline (speedup 1.0000x reference)
#include <cuda_runtime.h>
#include <cuda_bf16.h>
#include <cstdint>

#define T_TOKENS 16384
#define NEXP     64
#define KDIM     4096
#define BM       128        // tokens per CTA
#define KC       64         // K elems per chunk (2 x 32-K sub-blocks of 128B tf32 rows)
#define NCHUNK   (KDIM / KC)
#define THREADS  512

typedef unsigned long long u64;

#if defined(__CUDA_ARCH_FEAT_SM103_ALL) || defined(__CUDA_ARCH_FEAT_SM100_ALL) || defined(__CUDA_ARCH_FEAT_SM101_ALL)
#define HAS_TCGEN05 1
#else
#define HAS_TCGEN05 0
#endif

// ---- tf32 2-split geometry ----
// A (x) tile per chunk: [split:2][kblk:2][128 rows x 128B]  = 64 KB
// B (W) tile per chunk: [split:2][kblk:2][ 64 rows x 128B]  = 32 KB
#define A_SUB   (BM * 128)        // 16384
#define A_SPLIT (2 * A_SUB)       // 32768
#define A_ALL   (2 * A_SPLIT)     // 65536
#define B_SUB   (NEXP * 128)      // 8192
#define B_SPLIT (2 * B_SUB)       // 16384
#define B_CHUNK (2 * B_SPLIT)     // 32768
#define BUF_B   (A_ALL + B_CHUNK) // 98304
#define SMEM_DYN (1024 + 2 * BUF_B)  // 197632

// Precomputed W 2-split SW128 B-tile image per chunk (2 MB total, L2-resident)
__device__ uint4 Bimg[NCHUNK * B_CHUNK / 16];

#define SW128(o) ((o) ^ (((o) >> 3) & 0x70))

// ---------------- portable helpers ----------------
__device__ __forceinline__ u64 ffma2(u64 a, u64 b, u64 c) {
    u64 d; asm("fma.rn.f32x2 %0, %1, %2, %3;" : "=l"(d) : "l"(a), "l"(b), "l"(c)); return d;
}
__device__ __forceinline__ u64 pack2f(float lo, float hi) {
    u64 d; asm("mov.b64 %0, {%1, %2};" : "=l"(d) : "f"(lo), "f"(hi)); return d;
}
__device__ __forceinline__ void unpack2f(u64 v, float& lo, float& hi) {
    asm("mov.b64 {%0, %1}, %2;" : "=f"(lo), "=f"(hi) : "l"(v));
}
__device__ __forceinline__ uint32_t smem_u32(const void* p) {
    uint32_t a;
    asm("{ .reg .u64 t; cvta.to.shared.u64 t, %1; cvt.u32.u64 %0, t; }" : "=r"(a) : "l"(p));
    return a;
}
__device__ __forceinline__ void sts128(uint32_t a, uint32_t r0, uint32_t r1, uint32_t r2, uint32_t r3) {
    asm volatile("st.shared.v4.b32 [%0], {%1,%2,%3,%4};" :: "r"(a), "r"(r0), "r"(r1), "r"(r2), "r"(r3) : "memory");
}
__device__ __forceinline__ void cpasync16(uint32_t dst, const void* src) {
    asm volatile("cp.async.cg.shared.global [%0], [%1], 16;" :: "r"(dst), "l"(src) : "memory");
}
#define CP_COMMIT() asm volatile("cp.async.commit_group;" ::: "memory")
#define CP_WAIT0()  asm volatile("cp.async.wait_group 0;" ::: "memory")

// head/tail tf32 split: h = rna_tf32(x) (round-to-nearest head, exact tf32),
// l = x - h (exact in fp32; |l| <= 2^-11 |x|)
__device__ __forceinline__ void tf32split(float x, uint32_t& h, uint32_t& l) {
    uint32_t hb;
    asm("cvt.rna.tf32.f32 %0, %1;" : "=r"(hb) : "f"(x));
    h = hb;
    l = __float_as_uint(x - __uint_as_float(hb));
}

#if HAS_TCGEN05
// idesc kind::tf32: dtype=F32(1<<4), atype=TF32(2<<7), btype=TF32(2<<10), N/8<<17, M/16<<24
static constexpr uint32_t IDESC32 =
    (1u << 4) | (2u << 7) | (2u << 10) | ((NEXP / 8) << 17) | ((BM / 16) << 24); // 0x8100910

__device__ __forceinline__ uint32_t elect1() {
    uint32_t p;
    asm volatile("{ .reg .pred p; elect.sync _|p, 0xFFFFFFFF; selp.b32 %0,1,0,p; }" : "=r"(p));
    return p;
}
__device__ __forceinline__ u64 mkdesc(uint32_t addr) {  // SW128, LBO=1, SBO=64, version=1
    const u64 base = (2ULL << 61) | (1ULL << 46) | (64ULL << 32) | (1ULL << 16);
    return base | ((addr >> 4) & 0x3FFF);
}
__device__ __forceinline__ void mma_tf32_ss(uint32_t d, u64 ad, u64 bd, uint32_t en) {
    asm volatile(
        "{\n\t.reg .pred p;\n\tsetp.ne.u32 p, %5, 0;\n\t"
        "tcgen05.mma.cta_group::1.kind::tf32 [%0], %1, %2, %3, {%4,%4,%4,%4}, p;\n\t}"
        :: "r"(d), "l"(ad), "l"(bd), "r"(IDESC32), "r"(0u), "r"(en) : "memory");
}
#define MBAR_INIT(a, n) asm volatile("mbarrier.init.shared.b64 [%0], %1;" :: "r"(a), "r"(n) : "memory")
#define TCG_COMMIT(a) \
    asm volatile("tcgen05.commit.cta_group::1.mbarrier::arrive::one.shared::cluster.b64 [%0];" \
                 :: "r"(a) : "memory")
#define MBAR_WAIT(mbar, par) do {                                                   \
    uint32_t _m = (mbar), _p = (uint32_t)(par), _d;                                 \
    asm volatile("{\n\t.reg .pred p;\n\t"                                           \
        "mbarrier.try_wait.parity.acquire.cta.shared::cta.b64 p, [%1], %2;\n\t"     \
        "selp.b32 %0, 1, 0, p;\n\t}" : "=r"(_d) : "r"(_m), "r"(_p) : "memory");     \
    if (!_d) {                                                                      \
        asm volatile("{\n\t.reg .pred P1;\n\t"                                      \
            "W_%=:\n\t"                                                             \
            "mbarrier.try_wait.parity.acquire.cta.shared::cta.b64 P1, [%0], %1, 0x989680;\n\t" \
            "@P1 bra.uni D_%=;\n\t"                                                 \
            "bra.uni W_%=;\n\t"                                                     \
            "D_%=:\n\t}" :: "r"(_m), "r"(_p) : "memory");                           \
    } } while (0)
#define TCG_ALLOC(sm, n)  asm volatile("tcgen05.alloc.cta_group::1.sync.aligned.shared::cta.b32 [%0], %1;" :: "r"(sm), "r"(n) : "memory")
#define TCG_RELINQ()      asm volatile("tcgen05.relinquish_alloc_permit.cta_group::1.sync.aligned;")
#define TCG_DEALLOC(t, n) asm volatile("tcgen05.dealloc.cta_group::1.sync.aligned.b32 %0, %1;" :: "r"(t), "r"(n))
#define TCG_FENCE_AFTER() asm volatile("tcgen05.fence::after_thread_sync;" ::: "memory")
#define TCG_WAIT_LD()     asm volatile("tcgen05.wait::ld.sync.aligned;" ::: "memory")

#define LDTM32(r, addr) \
    asm volatile("tcgen05.ld.sync.aligned.32x32b.x32.b32 " \
        "{%0,%1,%2,%3,%4,%5,%6,%7,%8,%9,%10,%11,%12,%13,%14,%15," \
        "%16,%17,%18,%19,%20,%21,%22,%23,%24,%25,%26,%27,%28,%29,%30,%31}, [%32];" \
        : "=r"((r)[0]),"=r"((r)[1]),"=r"((r)[2]),"=r"((r)[3]),"=r"((r)[4]),"=r"((r)[5]), \
          "=r"((r)[6]),"=r"((r)[7]),"=r"((r)[8]),"=r"((r)[9]),"=r"((r)[10]),"=r"((r)[11]), \
          "=r"((r)[12]),"=r"((r)[13]),"=r"((r)[14]),"=r"((r)[15]),"=r"((r)[16]),"=r"((r)[17]), \
          "=r"((r)[18]),"=r"((r)[19]),"=r"((r)[20]),"=r"((r)[21]),"=r"((r)[22]),"=r"((r)[23]), \
          "=r"((r)[24]),"=r"((r)[25]),"=r"((r)[26]),"=r"((r)[27]),"=r"((r)[28]),"=r"((r)[29]), \
          "=r"((r)[30]),"=r"((r)[31]) : "r"(addr))
#endif  // HAS_TCGEN05

// ---------------- W tf32-2-split B-tile image precompute ----------------
__global__ void wimg_kernel(const float* __restrict__ W) {
#if HAS_TCGEN05
    int idx = blockIdx.x * blockDim.x + threadIdx.x;   // (chunk, expert, 16B group)
    if (idx >= NCHUNK * NEXP * 16) return;
    int c = idx >> 10;            // / (64*16)
    int r = (idx >> 4) & 63;      // expert row
    int j = idx & 15;             // 16B group within 64-K chunk (4 floats)
    int kblk = j >> 3, jc = j & 7;
    const float* p = W + (size_t)r * KDIM + c * KC + j * 4;
    uint4 h, l;
    tf32split(p[0], h.x, l.x);
    tf32split(p[1], h.y, l.y);
    tf32split(p[2], h.z, l.z);
    tf32split(p[3], h.w, l.w);
    uint32_t off = SW128((uint32_t)(r * 128 + jc * 16));
    uint4* base = &Bimg[((size_t)c * B_CHUNK) >> 4];
    base[(0 * B_SPLIT + kblk * B_SUB + off) >> 4] = h;
    base[(1 * B_SPLIT + kblk * B_SUB + off) >> 4] = l;
#endif
}

// ---------------- main fused kernel ----------------
__global__ __launch_bounds__(THREADS, 1)
void router_mma(const float* __restrict__ x,
                const float* __restrict__ W,
                float* __restrict__ out)
{
#if HAS_TCGEN05
    extern __shared__ char dsm[];
    __shared__ uint32_t s_tmem;
    __shared__ __align__(8) u64 s_mbar[2];

    const int tid = threadIdx.x;
    const int wid = tid >> 5, lid = tid & 31;
    const int t0 = blockIdx.x * BM;

    const uint32_t dbase = (smem_u32(dsm) + 1023u) & ~1023u;

    if (wid == 0) TCG_ALLOC(smem_u32(&s_tmem), 128);
    if (tid == 0) { MBAR_INIT(smem_u32(&s_mbar[0]), 1); MBAR_INIT(smem_u32(&s_mbar[1]), 1); }
    __syncthreads();
    const uint32_t tmem = s_tmem;
    if (wid == 0) TCG_RELINQ();
    const uint32_t mb0 = smem_u32(&s_mbar[0]);
    const uint32_t mb1 = smem_u32(&s_mbar[1]);
    int ph0 = 0, ph1 = 0;

    // per-thread x positions: idx = tid + i*512 -> row = idx>>4, 16B group c4 = idx&15
    const float* xbase = x + (size_t)t0 * KDIM;
    float4 xr[4];
#pragma unroll
    for (int i = 0; i < 4; i++) {
        int idx = tid + i * THREADS;
        int row = idx >> 4, c4 = idx & 15;
        xr[i] = *(const float4*)(xbase + (size_t)row * KDIM + c4 * 4);
    }

#pragma unroll 1
    for (int c = 0; c < NCHUNK; ++c) {
        float4 xn[4];
        if (c + 1 < NCHUNK) {
            const float* xp = xbase + (c + 1) * KC;
#pragma unroll
            for (int i = 0; i < 4; i++) {
                int idx = tid + i * THREADS;
                int row = idx >> 4, c4 = idx & 15;
                xn[i] = *(const float4*)(xp + (size_t)row * KDIM + c4 * 4);
            }
        }

        const int buf = c & 1;
        if (c >= 2) {
            if (buf == 0) { MBAR_WAIT(mb0, ph0); ph0 ^= 1; }
            else          { MBAR_WAIT(mb1, ph1); ph1 ^= 1; }
        }

        const uint32_t aB = dbase + (uint32_t)buf * BUF_B;
        const uint32_t bB = aB + A_ALL;

        // B tile: linear 32KB cp.async copy of precomputed swizzled image
        {
            const char* src = (const char*)Bimg + (size_t)c * B_CHUNK;
#pragma unroll
            for (int i = 0; i < 4; i++) {
                int idx = tid + i * THREADS;          // 0..2047 16B units
                cpasync16(bB + idx * 16, src + idx * 16);
            }
            CP_COMMIT();
        }

        // x -> 2 tf32 splits (rna head + exact tail) -> smem (SW128), STS.128 each
#pragma unroll
        for (int i = 0; i < 4; i++) {
            int idx = tid + i * THREADS;
            int row = idx >> 4, c4 = idx & 15;
            int kblk = c4 >> 3, jc = c4 & 7;
            uint4 h, l;
            tf32split(xr[i].x, h.x, l.x);
            tf32split(xr[i].y, h.y, l.y);
            tf32split(xr[i].z, h.z, l.z);
            tf32split(xr[i].w, h.w, l.w);
            uint32_t off = SW128((uint32_t)(row * 128 + jc * 16)) + (uint32_t)kblk * A_SUB;
            sts128(aB + 0 * A_SPLIT + off, h.x, h.y, h.z, h.w);
            sts128(aB + 1 * A_SPLIT + off, l.x, l.y, l.z, l.w);
        }

        CP_WAIT0();
        asm volatile("fence.proxy.async.shared::cta;" ::: "memory");
        __syncthreads();

        if (wid == 0 && elect1()) {
            // all 4 products: (h,wh), (h,wl), (l,wh), (l,wl)
            // each over 2 kblks x 4 K-steps (K=8 per dispatch)
#pragma unroll
            for (int pr = 0; pr < 4; pr++) {
                int sa = pr >> 1;          // a split: h,h,l,l
                int sb = pr & 1;           // b split: wh,wl,wh,wl
#pragma unroll
                for (int kb = 0; kb < 2; kb++) {
                    u64 ad = mkdesc(aB + sa * A_SPLIT + kb * A_SUB);
                    u64 bd = mkdesc(bB + sb * B_SPLIT + kb * B_SUB);
#pragma unroll
                    for (int ks = 0; ks < 4; ks++) {
                        u64 o = 2 * ks;
                        mma_tf32_ss(tmem, ad + o, bd + o,
                                    (c == 0 && pr == 0 && kb == 0 && ks == 0) ? 0u : 1u);
                    }
                }
            }
            TCG_COMMIT(buf == 0 ? mb0 : mb1);
        }

        if (c + 1 < NCHUNK) {
#pragma unroll
            for (int i = 0; i < 4; i++) xr[i] = xn[i];
        }
    }

    MBAR_WAIT(mb0, ph0);
    MBAR_WAIT(mb1, ph1);
    TCG_FENCE_AFTER();

    if (wid < 4) {   // warps 0-3: lane = token row in the 128x64 TMEM D
        uint32_t dr[64];
        LDTM32(dr, tmem);
        LDTM32(dr + 32, tmem + 32);
        TCG_WAIT_LD();

        float fv[NEXP];
#pragma unroll
        for (int e = 0; e < NEXP; e++) fv[e] = __uint_as_float(dr[e]);

        float b1 = -3.4e38f; int i1 = 0;
#pragma unroll
        for (int e = 0; e < NEXP; e++) if (fv[e] > b1) { b1 = fv[e]; i1 = e; }
        float b2 = -3.4e38f; int i2 = 0;
#pragma unroll
        for (int e = 0; e < NEXP; e++) if (e != i1 && fv[e] > b2) { b2 = fv[e]; i2 = e; }

        float s1 = 1.0f / (1.0f + expf(b2 - b1));
        float s2 = 1.0f - s1;

        int t = t0 + wid * 32 + lid;
        out[2 * t + 0] = s1;
        out[2 * t + 1] = s2;
        out[2 * T_TOKENS + 2 * t + 0] = (float)i1;
        out[2 * T_TOKENS + 2 * t + 1] = (float)i2;
    }

    __syncthreads();
    if (wid == 0) TCG_DEALLOC(tmem, 128);

#else
    // ============== fallback: proven FFMA f32x2 path (generic sm_103) ==============
    extern __shared__ char dsm[];
    struct SmG { float xs[32][64 + 2]; float ws[32][64 + 4]; };
    typedef float SmL[64][64 + 1];
    SmG* g  = (SmG*)dsm;
    SmL* lg = (SmL*)dsm;

    const int tid = threadIdx.x;
    if (tid >= 256) return;
    const int tm = (tid >> 4) << 2;
    const int tn = (tid & 15) << 2;

#pragma unroll 1
    for (int h = 0; h < 2; h++) {
        const int t0 = blockIdx.x * BM + h * 64;

        u64 acc[2][4];
#pragma unroll
        for (int p = 0; p < 2; p++)
#pragma unroll
            for (int j = 0; j < 4; j++) acc[p][j] = 0ULL;

        __syncthreads();

#pragma unroll 1
        for (int kb = 0; kb < KDIM; kb += 32) {
#pragma unroll
            for (int i = 0; i < 2; i++) {
                int idx = tid + i * 256;
                int row = idx >> 3;
                int c4  = (idx & 7) << 2;
                float4 v = *(const float4*)&x[(size_t)(t0 + row) * KDIM + kb + c4];
                g->xs[c4 + 0][row] = v.x;
                g->xs[c4 + 1][row] = v.y;
                g->xs[c4 + 2][row] = v.z;
                g->xs[c4 + 3][row] = v.w;
                float4 wv = *(const float4*)&W[(size_t)row * KDIM + kb + c4];
                g->ws[c4 + 0][row] = wv.x;
                g->ws[c4 + 1][row] = wv.y;
                g->ws[c4 + 2][row] = wv.z;
                g->ws[c4 + 3][row] = wv.w;
            }
            __syncthreads();

#pragma unroll
            for (int k = 0; k < 32; k++) {
                u64 x01 = *(const u64*)&g->xs[k][tm];
                u64 x23 = *(const u64*)&g->xs[k][tm + 2];
                float4 wv = *(const float4*)&g->ws[k][tn];
                u64 w0 = pack2f(wv.x, wv.x);
                u64 w1 = pack2f(wv.y, wv.y);
                u64 w2 = pack2f(wv.z, wv.z);
                u64 w3 = pack2f(wv.w, wv.w);
                acc[0][0] = ffma2(x01, w0, acc[0][0]);
                acc[1][0] = ffma2(x23, w0, acc[1][0]);
                acc[0][1] = ffma2(x01, w1, acc[0][1]);
                acc[1][1] = ffma2(x23, w1, acc[1][1]);
                acc[0][2] = ffma2(x01, w2, acc[0][2]);
                acc[1][2] = ffma2(x23, w2, acc[1][2]);
                acc[0][3] = ffma2(x01, w3, acc[0][3]);
                acc[1][3] = ffma2(x23, w3, acc[1][3]);
            }
            __syncthreads();
        }

#pragma unroll
        for (int p = 0; p < 2; p++)
#pragma unroll
            for (int j = 0; j < 4; j++) {
                float lo, hi;
                unpack2f(acc[p][j], lo, hi);
                (*lg)[tm + 2 * p + 0][tn + j] = lo;
                (*lg)[tm + 2 * p + 1][tn + j] = hi;
            }
        __syncthreads();

        if (tid < 64) {
            const float* row = (*lg)[tid];
            float b1 = -3.4e38f; int i1 = 0;
#pragma unroll 8
            for (int e = 0; e < NEXP; e++) {
                float v = row[e];
                if (v > b1) { b1 = v; i1 = e; }
            }
            float b2 = -3.4e38f; int i2 = 0;
#pragma unroll 8
            for (int e = 0; e < NEXP; e++) {
                if (e == i1) continue;
                float v = row[e];
                if (v > b2) { b2 = v; i2 = e; }
            }
            float s1 = 1.0f / (1.0f + expf(b2 - b1));
            float s2 = 1.0f - s1;

            int t = t0 + tid;
            out[2 * t + 0] = s1;
            out[2 * t + 1] = s2;
            out[2 * T_TOKENS + 2 * t + 0] = (float)i1;
            out[2 * T_TOKENS + 2 * t + 1] = (float)i2;
        }
    }
#endif
}

extern "C" void kernel_launch(void* const* d_in, const int* in_sizes, int n_in,
                              void* d_out, int out_size) {
    const float* x = (const float*)d_in[0];
    const float* W = (const float*)d_in[1];
    float* out = (float*)d_out;

    cudaFuncSetAttribute(router_mma, cudaFuncAttributeMaxDynamicSharedMemorySize, SMEM_DYN);

    wimg_kernel<<<(NCHUNK * NEXP * 16 + 255) / 256, 256>>>(W);
    router_mma<<<T_TOKENS / BM, THREADS, SMEM_DYN>>>(x, W, out);
}

// round 16
// speedup vs baseline: 1.5046x; 1.5046x over previous
#include <cuda_runtime.h>
#include <cuda_bf16.h>
#include <cstdint>

#define T_TOKENS 16384
#define NEXP     64
#define KDIM     4096
#define BM       128        // tokens per CTA (M=128 MMA, proven layout)
#define KSPLIT   2
#define KHALF    (KDIM / KSPLIT)      // 2048
#define KC       64                    // K elems per chunk
#define NC_CTA   (KHALF / KC)          // 32 chunks per CTA
#define NCHUNK   (KDIM / KC)           // 64 total
#define THREADS  256

typedef unsigned long long u64;

#if defined(__CUDA_ARCH_FEAT_SM103_ALL) || defined(__CUDA_ARCH_FEAT_SM100_ALL) || defined(__CUDA_ARCH_FEAT_SM101_ALL)
#define HAS_TCGEN05 1
#else
#define HAS_TCGEN05 0
#endif

// Precomputed W-split B-tile image per chunk: 3 splits x 64 rows x 128B = 24KB
#define B_TILE   (NEXP * 128)           // 8192
#define B_CHUNK  (3 * B_TILE)           // 24576
__device__ u64 Bimg[NCHUNK * B_CHUNK / 8];

// Partial logits scratch: [ksplit][token][expert] fp32 = 8MB
__device__ float Pscr[KSPLIT][T_TOKENS][NEXP];

#define A_TILE  (BM * 128)              // 16384 per split
#define A_ALL   (3 * A_TILE)            // 49152
#define SMEM_DYN (1024 + A_ALL + B_CHUNK)   // 74752 -> 2 CTAs/SM

#define SW128(o) ((o) ^ (((o) >> 3) & 0x70))

// ---------------- portable helpers ----------------
__device__ __forceinline__ u64 ffma2(u64 a, u64 b, u64 c) {
    u64 d; asm("fma.rn.f32x2 %0, %1, %2, %3;" : "=l"(d) : "l"(a), "l"(b), "l"(c)); return d;
}
__device__ __forceinline__ u64 pack2f(float lo, float hi) {
    u64 d; asm("mov.b64 %0, {%1, %2};" : "=l"(d) : "f"(lo), "f"(hi)); return d;
}
__device__ __forceinline__ void unpack2f(u64 v, float& lo, float& hi) {
    asm("mov.b64 {%0, %1}, %2;" : "=f"(lo), "=f"(hi) : "l"(v));
}
__device__ __forceinline__ uint32_t cvt_bf2(float lo, float hi) {
    uint32_t r; asm("cvt.rn.bf16x2.f32 %0, %1, %2;" : "=r"(r) : "f"(hi), "f"(lo)); return r;
}
__device__ __forceinline__ u64 bf2_to_f2(uint32_t p) {
    uint32_t lo = p << 16, hi = p & 0xFFFF0000u;
    u64 d; asm("mov.b64 %0, {%1, %2};" : "=l"(d) : "r"(lo), "r"(hi)); return d;
}
__device__ __forceinline__ u64 pk32(uint32_t lo, uint32_t hi) {
    u64 d; asm("mov.b64 %0, {%1, %2};" : "=l"(d) : "r"(lo), "r"(hi)); return d;
}
__device__ __forceinline__ uint32_t smem_u32(const void* p) {
    uint32_t a;
    asm("{ .reg .u64 t; cvta.to.shared.u64 t, %1; cvt.u32.u64 %0, t; }" : "=r"(a) : "l"(p));
    return a;
}
__device__ __forceinline__ void sts64(uint32_t a, u64 v) {
    asm volatile("st.shared.b64 [%0], %1;" :: "r"(a), "l"(v) : "memory");
}
__device__ __forceinline__ void cpasync16(uint32_t dst, const void* src) {
    asm volatile("cp.async.cg.shared.global [%0], [%1], 16;" :: "r"(dst), "l"(src) : "memory");
}
#define CP_COMMIT() asm volatile("cp.async.commit_group;" ::: "memory")
#define CP_WAIT0()  asm volatile("cp.async.wait_group 0;" ::: "memory")

// 3-way bf16 split of two adjacent floats -> three packed bf16x2 words
__device__ __forceinline__ void split3_2(float a, float b,
                                         uint32_t& q0, uint32_t& q1, uint32_t& q2) {
    const u64 M1 = 0xBF800000BF800000ULL;  // {-1.0f, -1.0f}
    u64 xp = pack2f(a, b);
    q0 = cvt_bf2(a, b);
    u64 r1 = ffma2(bf2_to_f2(q0), M1, xp);
    float r1l, r1h; unpack2f(r1, r1l, r1h);
    q1 = cvt_bf2(r1l, r1h);
    u64 r2 = ffma2(bf2_to_f2(q1), M1, r1);
    float r2l, r2h; unpack2f(r2, r2l, r2h);
    q2 = cvt_bf2(r2l, r2h);
}

#if HAS_TCGEN05
// idesc kind::f16: dtype=F32, atype=BF16, btype=BF16, N=64, M=128  (proven)
static constexpr uint32_t IDESC =
    (1u << 4) | (1u << 7) | (1u << 10) | ((NEXP / 8) << 17) | ((BM / 16) << 24); // 0x8100490

__device__ __forceinline__ uint32_t elect1() {
    uint32_t p;
    asm volatile("{ .reg .pred p; elect.sync _|p, 0xFFFFFFFF; selp.b32 %0,1,0,p; }" : "=r"(p));
    return p;
}
__device__ __forceinline__ u64 mkdesc(uint32_t addr) {  // SW128, LBO=1, SBO=64, version=1
    const u64 base = (2ULL << 61) | (1ULL << 46) | (64ULL << 32) | (1ULL << 16);
    return base | ((addr >> 4) & 0x3FFF);
}
__device__ __forceinline__ void mma_f16_ss(uint32_t d, u64 ad, u64 bd, uint32_t en) {
    asm volatile(
        "{\n\t.reg .pred p;\n\tsetp.ne.u32 p, %5, 0;\n\t"
        "tcgen05.mma.cta_group::1.kind::f16 [%0], %1, %2, %3, {%4,%4,%4,%4}, p;\n\t}"
        :: "r"(d), "l"(ad), "l"(bd), "r"(IDESC), "r"(0u), "r"(en) : "memory");
}
#define MBAR_INIT(a, n) asm volatile("mbarrier.init.shared.b64 [%0], %1;" :: "r"(a), "r"(n) : "memory")
#define TCG_COMMIT(a) \
    asm volatile("tcgen05.commit.cta_group::1.mbarrier::arrive::one.shared::cluster.b64 [%0];" \
                 :: "r"(a) : "memory")
#define MBAR_WAIT(mbar, par) do {                                                   \
    uint32_t _m = (mbar), _p = (uint32_t)(par), _d;                                 \
    asm volatile("{\n\t.reg .pred p;\n\t"                                           \
        "mbarrier.try_wait.parity.acquire.cta.shared::cta.b64 p, [%1], %2;\n\t"     \
        "selp.b32 %0, 1, 0, p;\n\t}" : "=r"(_d) : "r"(_m), "r"(_p) : "memory");     \
    if (!_d) {                                                                      \
        asm volatile("{\n\t.reg .pred P1;\n\t"                                      \
            "W_%=:\n\t"                                                             \
            "mbarrier.try_wait.parity.acquire.cta.shared::cta.b64 P1, [%0], %1, 0x989680;\n\t" \
            "@P1 bra.uni D_%=;\n\t"                                                 \
            "bra.uni W_%=;\n\t"                                                     \
            "D_%=:\n\t}" :: "r"(_m), "r"(_p) : "memory");                           \
    } } while (0)
#define TCG_ALLOC(sm, n)  asm volatile("tcgen05.alloc.cta_group::1.sync.aligned.shared::cta.b32 [%0], %1;" :: "r"(sm), "r"(n) : "memory")
#define TCG_RELINQ()      asm volatile("tcgen05.relinquish_alloc_permit.cta_group::1.sync.aligned;")
#define TCG_DEALLOC(t, n) asm volatile("tcgen05.dealloc.cta_group::1.sync.aligned.b32 %0, %1;" :: "r"(t), "r"(n))
#define TCG_FENCE_AFTER() asm volatile("tcgen05.fence::after_thread_sync;" ::: "memory")
#define TCG_WAIT_LD()     asm volatile("tcgen05.wait::ld.sync.aligned;" ::: "memory")

#define LDTM32(r, addr) \
    asm volatile("tcgen05.ld.sync.aligned.32x32b.x32.b32 " \
        "{%0,%1,%2,%3,%4,%5,%6,%7,%8,%9,%10,%11,%12,%13,%14,%15," \
        "%16,%17,%18,%19,%20,%21,%22,%23,%24,%25,%26,%27,%28,%29,%30,%31}, [%32];" \
        : "=r"((r)[0]),"=r"((r)[1]),"=r"((r)[2]),"=r"((r)[3]),"=r"((r)[4]),"=r"((r)[5]), \
          "=r"((r)[6]),"=r"((r)[7]),"=r"((r)[8]),"=r"((r)[9]),"=r"((r)[10]),"=r"((r)[11]), \
          "=r"((r)[12]),"=r"((r)[13]),"=r"((r)[14]),"=r"((r)[15]),"=r"((r)[16]),"=r"((r)[17]), \
          "=r"((r)[18]),"=r"((r)[19]),"=r"((r)[20]),"=r"((r)[21]),"=r"((r)[22]),"=r"((r)[23]), \
          "=r"((r)[24]),"=r"((r)[25]),"=r"((r)[26]),"=r"((r)[27]),"=r"((r)[28]),"=r"((r)[29]), \
          "=r"((r)[30]),"=r"((r)[31]) : "r"(addr))
#endif  // HAS_TCGEN05

// ---------------- W split B-tile image precompute ----------------
__global__ void wimg_kernel(const float* __restrict__ W) {
#if HAS_TCGEN05
    int idx = blockIdx.x * blockDim.x + threadIdx.x;   // (chunk, expert, u64 group)
    if (idx >= NCHUNK * NEXP * 16) return;
    int c = idx >> 10;
    int r = (idx >> 4) & 63;
    int j = idx & 15;
    const float* p = W + (size_t)r * KDIM + c * KC + j * 4;
    uint32_t a0, a1, a2, b0, b1, b2;
    split3_2(p[0], p[1], a0, a1, a2);
    split3_2(p[2], p[3], b0, b1, b2);
    uint32_t off = SW128((uint32_t)(r * 128 + j * 8));
    u64* base = &Bimg[((size_t)c * B_CHUNK) >> 3];
    base[(0 * B_TILE + off) >> 3] = pk32(a0, b0);
    base[(1 * B_TILE + off) >> 3] = pk32(a1, b1);
    base[(2 * B_TILE + off) >> 3] = pk32(a2, b2);
#endif
}

// ---------------- main GEMM kernel (K-split partials) ----------------
__global__ __launch_bounds__(THREADS, 2)
void router_mma(const float* __restrict__ x,
                const float* __restrict__ W)
{
    const int bx = blockIdx.x;
    const int tb = bx >> 1;           // token tile 0..127
    const int ks = bx & 1;            // K-split half
    const int t0 = tb * BM;
    const int c0 = ks * NC_CTA;       // absolute chunk base

#if HAS_TCGEN05
    extern __shared__ char dsm[];
    __shared__ uint32_t s_tmem;
    __shared__ __align__(8) u64 s_mbar;

    const int tid = threadIdx.x;
    const int wid = tid >> 5, lid = tid & 31;

    const uint32_t dbase = (smem_u32(dsm) + 1023u) & ~1023u;
    const uint32_t aB = dbase;
    const uint32_t bB = dbase + A_ALL;

    if (wid == 0) TCG_ALLOC(smem_u32(&s_tmem), 128);
    if (tid == 0) MBAR_INIT(smem_u32(&s_mbar), 1);
    __syncthreads();
    const uint32_t tmem = s_tmem;
    if (wid == 0) TCG_RELINQ();
    const uint32_t mb = smem_u32(&s_mbar);
    int ph = 0;

    const float* xbase = x + (size_t)t0 * KDIM + (size_t)ks * KHALF;

#pragma unroll 1
    for (int c = 0; c < NC_CTA; ++c) {
        // issue x LDGs for THIS chunk first (registers only) — their latency
        // overlaps the MBAR_WAIT for the previous chunk's MMA.
        // 8 x 256 threads x float4 = 2048 float4 = full 128 rows x 64 K.
        float4 xr[8];
        {
            const float* xp = xbase + c * KC;
#pragma unroll
            for (int i = 0; i < 8; i++) {
                int idx = tid + i * THREADS;
                int row = idx >> 4, c4 = idx & 15;
                xr[i] = *(const float4*)(xp + (size_t)row * KDIM + c4 * 4);
            }
        }

        // single-buffered A/B: previous chunk's MMA must be fully done
        if (c >= 1) { MBAR_WAIT(mb, ph); ph ^= 1; }

        // B tile: linear 24KB cp.async copy of the precomputed swizzled image
        {
            const char* src = (const char*)Bimg + (size_t)(c0 + c) * B_CHUNK;
#pragma unroll
            for (int i = 0; i < 6; i++) {
                int idx = tid + i * THREADS;          // 0..1535 16B units
                cpasync16(bB + idx * 16, src + idx * 16);
            }
            CP_COMMIT();
        }

        // x -> 3 bf16 splits -> smem (SW128), full 128 rows
#pragma unroll
        for (int i = 0; i < 8; i++) {
            int idx = tid + i * THREADS;
            int row = idx >> 4, c4 = idx & 15;
            uint32_t q0a, q1a, q2a, q0b, q1b, q2b;
            split3_2(xr[i].x, xr[i].y, q0a, q1a, q2a);
            split3_2(xr[i].z, xr[i].w, q0b, q1b, q2b);
            uint32_t off = SW128((uint32_t)(row * 128 + c4 * 8));
            sts64(aB + 0 * A_TILE + off, pk32(q0a, q0b));
            sts64(aB + 1 * A_TILE + off, pk32(q1a, q1b));
            sts64(aB + 2 * A_TILE + off, pk32(q2a, q2b));
        }

        CP_WAIT0();
        asm volatile("fence.proxy.async.shared::cta;" ::: "memory");
        __syncthreads();   // all STS/cp.async visible before MMA issue

        if (wid == 0 && elect1()) {
            u64 ad0 = mkdesc(aB), ad1 = mkdesc(aB + A_TILE), ad2 = mkdesc(aB + 2 * A_TILE);
            u64 bd0 = mkdesc(bB), bd1 = mkdesc(bB + B_TILE), bd2 = mkdesc(bB + 2 * B_TILE);
#pragma unroll
            for (int kstep = 0; kstep < 4; kstep++) {   // K=16 per dispatch
                u64 o = 2 * kstep;
                mma_f16_ss(tmem, ad0 + o, bd0 + o, (c == 0 && kstep == 0) ? 0u : 1u);
                mma_f16_ss(tmem, ad0 + o, bd1 + o, 1u);
                mma_f16_ss(tmem, ad1 + o, bd0 + o, 1u);
                mma_f16_ss(tmem, ad0 + o, bd2 + o, 1u);
                mma_f16_ss(tmem, ad1 + o, bd1 + o, 1u);
                mma_f16_ss(tmem, ad2 + o, bd0 + o, 1u);
            }
            TCG_COMMIT(mb);
        }
        // no post-commit sync: next chunk's STS is ordered by MBAR_WAIT
    }

    MBAR_WAIT(mb, ph);
    TCG_FENCE_AFTER();

    if (wid < 4) {   // M=128: lane = token row (proven layout)
        uint32_t dr[64];
        LDTM32(dr, tmem);
        LDTM32(dr + 32, tmem + 32);
        TCG_WAIT_LD();

        int t = t0 + wid * 32 + lid;
        float4* dst = (float4*)&Pscr[ks][t][0];
#pragma unroll
        for (int j = 0; j < 16; j++) {
            float4 v;
            v.x = __uint_as_float(dr[4 * j + 0]);
            v.y = __uint_as_float(dr[4 * j + 1]);
            v.z = __uint_as_float(dr[4 * j + 2]);
            v.w = __uint_as_float(dr[4 * j + 3]);
            dst[j] = v;
        }
    }

    __syncthreads();
    if (wid == 0) TCG_DEALLOC(tmem, 128);

#else
    // ============== fallback: FFMA f32x2 partials over this CTA's K-half ==============
    extern __shared__ char dsm[];
    struct SmG { float xs[32][64 + 2]; float ws[32][64 + 4]; };
    SmG* g = (SmG*)dsm;

    const int tid = threadIdx.x;
    const int tm = (tid >> 4) << 2;
    const int tn = (tid & 15) << 2;

#pragma unroll 1
    for (int h = 0; h < 2; h++) {
        const int tt0 = t0 + h * 64;

        u64 acc[2][4];
#pragma unroll
        for (int p = 0; p < 2; p++)
#pragma unroll
            for (int j = 0; j < 4; j++) acc[p][j] = 0ULL;

        __syncthreads();

#pragma unroll 1
        for (int kb = ks * KHALF; kb < (ks + 1) * KHALF; kb += 32) {
#pragma unroll
            for (int i = 0; i < 2; i++) {
                int idx = tid + i * 256;
                int row = idx >> 3;
                int c4  = (idx & 7) << 2;
                float4 v = *(const float4*)&x[(size_t)(tt0 + row) * KDIM + kb + c4];
                g->xs[c4 + 0][row] = v.x;
                g->xs[c4 + 1][row] = v.y;
                g->xs[c4 + 2][row] = v.z;
                g->xs[c4 + 3][row] = v.w;
                float4 wv = *(const float4*)&W[(size_t)row * KDIM + kb + c4];
                g->ws[c4 + 0][row] = wv.x;
                g->ws[c4 + 1][row] = wv.y;
                g->ws[c4 + 2][row] = wv.z;
                g->ws[c4 + 3][row] = wv.w;
            }
            __syncthreads();

#pragma unroll
            for (int k = 0; k < 32; k++) {
                u64 x01 = *(const u64*)&g->xs[k][tm];
                u64 x23 = *(const u64*)&g->xs[k][tm + 2];
                float4 wv = *(const float4*)&g->ws[k][tn];
                u64 w0 = pack2f(wv.x, wv.x);
                u64 w1 = pack2f(wv.y, wv.y);
                u64 w2 = pack2f(wv.z, wv.z);
                u64 w3 = pack2f(wv.w, wv.w);
                acc[0][0] = ffma2(x01, w0, acc[0][0]);
                acc[1][0] = ffma2(x23, w0, acc[1][0]);
                acc[0][1] = ffma2(x01, w1, acc[0][1]);
                acc[1][1] = ffma2(x23, w1, acc[1][1]);
                acc[0][2] = ffma2(x01, w2, acc[0][2]);
                acc[1][2] = ffma2(x23, w2, acc[1][2]);
                acc[0][3] = ffma2(x01, w3, acc[0][3]);
                acc[1][3] = ffma2(x23, w3, acc[1][3]);
            }
            __syncthreads();
        }

        // write partial logits directly
#pragma unroll
        for (int p = 0; p < 2; p++)
#pragma unroll
            for (int j = 0; j < 4; j++) {
                float lo, hi;
                unpack2f(acc[p][j], lo, hi);
                Pscr[ks][tt0 + tm + 2 * p + 0][tn + j] = lo;
                Pscr[ks][tt0 + tm + 2 * p + 1][tn + j] = hi;
            }
    }
#endif
}

// ---------------- combine + top2 + softmax (portable, deterministic) ----------------
__global__ void combine_kernel(float* __restrict__ out) {
    int t = blockIdx.x * blockDim.x + threadIdx.x;
    if (t >= T_TOKENS) return;

    const float4* p0 = (const float4*)&Pscr[0][t][0];
    const float4* p1 = (const float4*)&Pscr[1][t][0];
    float fv[NEXP];
#pragma unroll
    for (int j = 0; j < 16; j++) {
        float4 a = p0[j], b = p1[j];
        fv[4 * j + 0] = a.x + b.x;
        fv[4 * j + 1] = a.y + b.y;
        fv[4 * j + 2] = a.z + b.z;
        fv[4 * j + 3] = a.w + b.w;
    }

    float b1 = -3.4e38f; int i1 = 0;
#pragma unroll
    for (int e = 0; e < NEXP; e++) if (fv[e] > b1) { b1 = fv[e]; i1 = e; }
    float b2 = -3.4e38f; int i2 = 0;
#pragma unroll
    for (int e = 0; e < NEXP; e++) if (e != i1 && fv[e] > b2) { b2 = fv[e]; i2 = e; }

    float s1 = 1.0f / (1.0f + expf(b2 - b1));
    float s2 = 1.0f - s1;

    out[2 * t + 0] = s1;
    out[2 * t + 1] = s2;
    out[2 * T_TOKENS + 2 * t + 0] = (float)i1;
    out[2 * T_TOKENS + 2 * t + 1] = (float)i2;
}

extern "C" void kernel_launch(void* const* d_in, const int* in_sizes, int n_in,
                              void* d_out, int out_size) {
    const float* x = (const float*)d_in[0];
    const float* W = (const float*)d_in[1];
    float* out = (float*)d_out;

    cudaFuncSetAttribute(router_mma, cudaFuncAttributeMaxDynamicSharedMemorySize, SMEM_DYN);

    wimg_kernel<<<(NCHUNK * NEXP * 16 + 255) / 256, 256>>>(W);
    router_mma<<<(T_TOKENS / BM) * KSPLIT, THREADS, SMEM_DYN>>>(x, W);
    combine_kernel<<<T_TOKENS / 256, 256>>>(out);
}